// round 8
// baseline (speedup 1.0000x reference)
#include <cuda_runtime.h>
#include <math.h>

// Problem constants
#define HH      256
#define NPOLES  32
#define LLEN    8192
#define LH      4097
#define MHALF   4096
#define KSTRIDE 4104       // padded row stride (16B-aligned rows)

// Scratch: half-spectrum k_f per (h, l). 256*4104*8B = 8.4 MB.
__device__ float2 g_kf[HH * KSTRIDE];

typedef unsigned long long u64;

// ---- packed f32x2 helpers (sm_100a) ---------------------------------------
__device__ __forceinline__ u64 f2add(u64 a, u64 b) {
    u64 d; asm("add.rn.f32x2 %0,%1,%2;" : "=l"(d) : "l"(a), "l"(b)); return d;
}
__device__ __forceinline__ u64 f2mul(u64 a, u64 b) {
    u64 d; asm("mul.rn.f32x2 %0,%1,%2;" : "=l"(d) : "l"(a), "l"(b)); return d;
}
__device__ __forceinline__ u64 f2fma(u64 a, u64 b, u64 c) {
    u64 d; asm("fma.rn.f32x2 %0,%1,%2,%3;" : "=l"(d) : "l"(a), "l"(b), "l"(c)); return d;
}
__device__ __forceinline__ u64 f2rcp(u64 a) {
    u64 d;
    asm("{\n\t.reg .f32 lo,hi,rl,rh;\n\t"
        "mov.b64 {lo,hi}, %1;\n\t"
        "rcp.approx.f32 rl, lo;\n\t"
        "rcp.approx.f32 rh, hi;\n\t"
        "mov.b64 %0, {rl,rh};\n\t}" : "=l"(d) : "l"(a));
    return d;
}
__device__ __forceinline__ u64 pack2(float x, float y) {
    u64 d; asm("mov.b64 %0, {%1,%2};" : "=l"(d) : "f"(x), "f"(y)); return d;
}
__device__ __forceinline__ void unpack2(u64 a, float& x, float& y) {
    asm("mov.b64 {%0,%1}, %2;" : "=f"(x), "=f"(y) : "l"(a));
}

// per-lane Woodbury epilogue (im accumulators arrive negated)
__device__ __forceinline__ float2 woodbury(
    float r00r, float n00, float r01r, float n01,
    float r10r, float n10, float r11r, float n11, float t)
{
    const float r00i = -n00, r01i = -n01, r10i = -n10, r11i = -n11;
    const float dre  = 1.0f + r11r;
    const float dim  = r11i;
    const float dinv = __frcp_rn(fmaf(dre, dre, dim * dim));
    const float numre = r01r * r10r - r01i * r10i;
    const float numim = r01r * r10i + r01i * r10r;
    const float qre = (numre * dre + numim * dim) * dinv;
    const float qim = (numim * dre - numre * dim) * dinv;
    const float kwre = r00r - qre;
    const float kwim = r00i - qim;
    return make_float2(kwre - kwim * t, fmaf(kwre, t, kwim));
}

// ---------------------------------------------------------------------------
// Kernel 1: Cauchy + rank-1 Woodbury + bilinear scale -> g_kf[h][l]
//
// z = i*zy, u = zy^2. Stable denominator: m = (u - aw)^2 + 4*wr^2*u.
// STABLE numerator split (no mixed cancellation of wr- and wi-scaled terms):
//   re  += C1*p1 + C2*p2      p1 = (u+aw)*iv,  p2 = (u-aw)*iv
//   imn += K1*gi + K2*ti      gi = (u+cw)*ti,  ti = zy*iv
// C1=-2dt*wr*vr, C2=2dt*wi*vi, K1=2dt*vr, K2=4dt*wr*wi*vi
// Const slots (u64): 0:AW 1:NAW 2:CW 3:FWR2; per e: 4+4e:C1 5:C2 6:K1 7:K2
// Each thread: 8 l's (4 packed pairs) -> constants amortized 4x.
// ---------------------------------------------------------------------------
__global__ __launch_bounds__(128) void cauchy_kernel(
    const float* __restrict__ w_re, const float* __restrict__ w_im,
    const float* __restrict__ p_re, const float* __restrict__ p_im,
    const float* __restrict__ B_re, const float* __restrict__ B_im,
    const float* __restrict__ C_re, const float* __restrict__ C_im,
    const float* __restrict__ log_dt)
{
    __shared__ float2 cst[NPOLES][20];

    const int h   = blockIdx.y;
    const int tid = threadIdx.x;

    if (tid < NPOLES) {
        const int n   = tid;
        const int idx = h * NPOLES + n;
        const float dt = expf(log_dt[h]);
        const float wr = w_re[idx] * dt;
        const float wi = w_im[idx] * dt;
        const float Br = B_re[idx], Bi = B_im[idx];
        const float Cr = C_re[idx], Ci = C_im[idx];
        const float Pr = p_re[idx], Pi = p_im[idx];
        const float aw = wr * wr + wi * wi;
        const float cw = wr * wr - wi * wi;
        const float d2 = 2.0f * dt;
        float2* cn = cst[n];
        cn[0] = make_float2(aw, aw);
        cn[1] = make_float2(-aw, -aw);
        cn[2] = make_float2(cw, cw);
        cn[3] = make_float2(4.0f * wr * wr, 4.0f * wr * wr);
        const float VR[4] = { Br * Cr - Bi * Ci,
                              Br * Pr + Bi * Pi,
                              Pr * Cr - Pi * Ci,
                              Pr * Pr + Pi * Pi };
        const float VI[4] = { Br * Ci + Bi * Cr,
                              Bi * Pr - Br * Pi,
                              Pr * Ci + Pi * Cr,
                              0.0f };
        #pragma unroll
        for (int e = 0; e < 4; e++) {
            float v;
            v = -d2 * wr * VR[e];             cn[4 + 4 * e] = make_float2(v, v); // C1
            v =  d2 * wi * VI[e];             cn[5 + 4 * e] = make_float2(v, v); // C2
            v =  d2 * VR[e];                  cn[6 + 4 * e] = make_float2(v, v); // K1
            v =  d2 * 2.0f * wr * wi * VI[e]; cn[7 + 4 * e] = make_float2(v, v); // K2
        }
    }
    __syncthreads();

    // Nyquist bin (z -> inf): k_f = sum_n dt*Re(B*C) = sum 0.5*K1_00
    if (blockIdx.x == 0 && tid == 0) {
        float acc = 0.0f;
        #pragma unroll
        for (int n = 0; n < NPOLES; n++) acc += 0.5f * cst[n][6].x;
        g_kf[h * KSTRIDE + MHALF] = make_float2(acc, 0.0f);
    }

    const int l0 = (blockIdx.x * 128 + tid) * 8;

    float tt[8];
    #pragma unroll
    for (int i = 0; i < 8; i++) {
        float s, c;
        sincospif((float)(l0 + i) * (1.0f / LLEN), &s, &c);
        tt[i] = __fdividef(s, c);
    }
    u64 zz[4], uu[4];
    #pragma unroll
    for (int pr = 0; pr < 4; pr++) {
        zz[pr] = pack2(2.0f * tt[2 * pr], 2.0f * tt[2 * pr + 1]);
        uu[pr] = f2mul(zz[pr], zz[pr]);
    }

    u64 accR[4][4], accN[4][4];
    #pragma unroll
    for (int pr = 0; pr < 4; pr++)
        #pragma unroll
        for (int e = 0; e < 4; e++) { accR[pr][e] = 0; accN[pr][e] = 0; }

    #pragma unroll 2
    for (int n = 0; n < NPOLES; n++) {
        const u64* cn = reinterpret_cast<const u64*>(cst[n]);
        const u64 AW   = cn[0];
        const u64 NAW  = cn[1];
        const u64 CW   = cn[2];
        const u64 FWR2 = cn[3];
        #pragma unroll
        for (int pr = 0; pr < 4; pr++) {
            const u64 u  = uu[pr];
            const u64 c1 = f2add(u, AW);
            const u64 c2 = f2add(u, NAW);
            const u64 c3 = f2add(u, CW);
            const u64 m  = f2fma(c2, c2, f2mul(u, FWR2));
            const u64 iv = f2rcp(m);
            const u64 ti = f2mul(zz[pr], iv);
            const u64 p1 = f2mul(c1, iv);
            const u64 p2 = f2mul(c2, iv);
            const u64 gi = f2mul(c3, ti);
            #pragma unroll
            for (int e = 0; e < 3; e++) {
                accR[pr][e] = f2fma(cn[4 + 4 * e], p1, f2fma(cn[5 + 4 * e], p2, accR[pr][e]));
                accN[pr][e] = f2fma(cn[6 + 4 * e], gi, f2fma(cn[7 + 4 * e], ti, accN[pr][e]));
            }
            accR[pr][3] = f2fma(cn[16], p1, accR[pr][3]);   // v11: vi = 0
            accN[pr][3] = f2fma(cn[18], gi, accN[pr][3]);
        }
    }

    // epilogue
    float rr[8][4], nn[8][4];   // [lane l][entry]
    #pragma unroll
    for (int pr = 0; pr < 4; pr++)
        #pragma unroll
        for (int e = 0; e < 4; e++) {
            unpack2(accR[pr][e], rr[2 * pr][e], rr[2 * pr + 1][e]);
            unpack2(accN[pr][e], nn[2 * pr][e], nn[2 * pr + 1][e]);
        }

    float2 kf[8];
    #pragma unroll
    for (int i = 0; i < 8; i++)
        kf[i] = woodbury(rr[i][0], nn[i][0], rr[i][1], nn[i][1],
                         rr[i][2], nn[i][2], rr[i][3], nn[i][3], tt[i]);

    float2* row = g_kf + h * KSTRIDE;
    #pragma unroll
    for (int i = 0; i < 4; i++)
        reinterpret_cast<float4*>(row + l0 + 2 * i)[0] =
            make_float4(kf[2 * i].x, kf[2 * i].y, kf[2 * i + 1].x, kf[2 * i + 1].y);
}

// ---------------------------------------------------------------------------
// Kernel 2: per-h irfft(8192) via M=4096 radix-8 Stockham inverse FFT.
// 4 stages (s = 1, 8, 64, 512), padded buffers, [k][p] twiddle tables.
// 256 threads/block, 2 butterflies per thread -> 2 blocks/SM, single wave.
// ---------------------------------------------------------------------------
#define PADIDX(i) ((i) + ((i) >> 3))
#define IFFT_T 256

__device__ __forceinline__ u64 csub(u64 a, u64 b) {
    const u64 NEG1 = 0xBF800000BF800000ULL;   // (-1.f, -1.f)
    return f2fma(b, NEG1, a);
}
__device__ __forceinline__ u64 cmuli(u64 a) {     // * i : (x,y) -> (-y,x)
    float x, y; unpack2(a, x, y);
    return pack2(-y, x);
}
__device__ __forceinline__ u64 cmul(u64 a, u64 w) {
    float ax, ay, wx, wy; unpack2(a, ax, ay); unpack2(w, wx, wy);
    return pack2(fmaf(ax, wx, -ay * wy), fmaf(ax, wy, ay * wx));
}

template<int S, int LS, int M, bool TW>
__device__ __forceinline__ void fft_butterfly(const float2* __restrict__ src,
                                              float2* __restrict__ dst,
                                              const float2* __restrict__ twt,
                                              int t)
{
    const int q = t & (S - 1);
    const int p = t >> LS;
    const int base = q + S * p;

    u64 x[8];
    #pragma unroll
    for (int j = 0; j < 8; j++)
        x[j] = *reinterpret_cast<const u64*>(&src[PADIDX(base + j * 512)]);

    // even DFT4 on (x0,x2,x4,x6); odd DFT4 on (x1,x3,x5,x7); sign +i (inverse)
    u64 ta = f2add(x[0], x[4]), tb = csub(x[0], x[4]);
    u64 tc = f2add(x[2], x[6]), td = csub(x[2], x[6]);
    u64 E0 = f2add(ta, tc), E2 = csub(ta, tc);
    u64 itd = cmuli(td);
    u64 E1 = f2add(tb, itd), E3 = csub(tb, itd);

    u64 oa = f2add(x[1], x[5]), ob = csub(x[1], x[5]);
    u64 oc = f2add(x[3], x[7]), od = csub(x[3], x[7]);
    u64 O0 = f2add(oa, oc), O2 = csub(oa, oc);
    u64 iod = cmuli(od);
    u64 O1 = f2add(ob, iod), O3 = csub(ob, iod);

    const float SQ = 0.70710678118654752f;
    float o1x, o1y, o3x, o3y;
    unpack2(O1, o1x, o1y); unpack2(O3, o3x, o3y);
    const u64 W1 = pack2(SQ * (o1x - o1y), SQ * (o1x + o1y));   // w^1 * O1
    const u64 W2 = cmuli(O2);                                    // w^2 * O2
    const u64 W3 = pack2(-SQ * (o3x + o3y), SQ * (o3x - o3y));   // w^3 * O3

    u64 y[8];
    y[0] = f2add(E0, O0); y[4] = csub(E0, O0);
    y[1] = f2add(E1, W1); y[5] = csub(E1, W1);
    y[2] = f2add(E2, W2); y[6] = csub(E2, W2);
    y[3] = f2add(E3, W3); y[7] = csub(E3, W3);

    const int obase = q + S * 8 * p;
    *reinterpret_cast<u64*>(&dst[PADIDX(obase)]) = y[0];
    #pragma unroll
    for (int k = 1; k < 8; k++) {
        u64 v = y[k];
        if (TW) {
            const u64 w = *reinterpret_cast<const u64*>(&twt[(k - 1) * M + p]);
            v = cmul(v, w);
        }
        *reinterpret_cast<u64*>(&dst[PADIDX(obase + S * k)]) = v;
    }
}

// smem (float2 units): bufA[4608] bufB[4608] tw1[3584] tw8[448] tw64[56]
#define SM_TOTAL_F2 (4608 + 4608 + 3584 + 448 + 56)

__global__ __launch_bounds__(IFFT_T) void ifft_kernel(float* __restrict__ out)
{
    extern __shared__ float2 sh[];
    float2* bufA = sh;
    float2* bufB = sh + 4608;
    float2* tw1  = sh + 9216;
    float2* tw8  = sh + 12800;
    float2* tw64 = sh + 13248;

    const int h   = blockIdx.x;
    const int tid = threadIdx.x;

    // build stage twiddle tables: [k-1][p] = e^{+2pi i p k / Nt}
    for (int i = tid; i < 3584; i += IFFT_T) {
        const int k = (i >> 9) + 1, p = i & 511;
        float s, c; sincospif((float)(p * k) * (1.0f / 2048.0f), &s, &c);
        tw1[i] = make_float2(c, s);
    }
    for (int i = tid; i < 448; i += IFFT_T) {
        const int k = (i >> 6) + 1, p = i & 63;
        float s, c; sincospif((float)(p * k) * (1.0f / 256.0f), &s, &c);
        tw8[i] = make_float2(c, s);
    }
    if (tid < 56) {
        const int k = (tid >> 3) + 1, p = tid & 7;
        float s, c; sincospif((float)(p * k) * (1.0f / 32.0f), &s, &c);
        tw64[tid] = make_float2(c, s);
    }

    // C2R unpack into bufA (padded), scale folded
    const float scale = 1.0f / (float)MHALF;
    const float2* __restrict__ K = &g_kf[h * KSTRIDE];
    for (int k = tid; k < MHALF; k += IFFT_T) {
        float2 Kk = K[k];
        float2 Km = K[MHALF - k];
        if (k == 0) { Kk.y = 0.0f; Km.y = 0.0f; }
        const float Ere = 0.5f * (Kk.x + Km.x);
        const float Eim = 0.5f * (Kk.y - Km.y);
        const float Dre = 0.5f * (Kk.x - Km.x);
        const float Dim = 0.5f * (Kk.y + Km.y);
        float tws, twc;
        sincospif((float)k * (1.0f / MHALF), &tws, &twc);   // e^{+2pi i k/8192}
        const float Ore = Dre * twc - Dim * tws;
        const float Oim = Dre * tws + Dim * twc;
        bufA[PADIDX(k)] = make_float2((Ere - Oim) * scale, (Eim + Ore) * scale);
    }
    __syncthreads();

    #pragma unroll
    for (int t = 0; t < 2; t++) fft_butterfly<1,   0, 512, true >(bufA, bufB, tw1,  tid + t * IFFT_T);
    __syncthreads();
    #pragma unroll
    for (int t = 0; t < 2; t++) fft_butterfly<8,   3, 64,  true >(bufB, bufA, tw8,  tid + t * IFFT_T);
    __syncthreads();
    #pragma unroll
    for (int t = 0; t < 2; t++) fft_butterfly<64,  6, 8,   true >(bufA, bufB, tw64, tid + t * IFFT_T);
    __syncthreads();
    #pragma unroll
    for (int t = 0; t < 2; t++) fft_butterfly<512, 9, 1,   false>(bufB, bufA, (const float2*)0, tid + t * IFFT_T);
    __syncthreads();

    float2* o2 = reinterpret_cast<float2*>(out) + (size_t)h * MHALF;
    for (int m2 = tid; m2 < MHALF; m2 += IFFT_T) {
        o2[m2] = bufA[PADIDX(m2)];
    }
}

// ---------------------------------------------------------------------------
extern "C" void kernel_launch(void* const* d_in, const int* in_sizes, int n_in,
                              void* d_out, int out_size)
{
    const float* w_re   = (const float*)d_in[0];
    const float* w_im   = (const float*)d_in[1];
    const float* p_re   = (const float*)d_in[2];
    const float* p_im   = (const float*)d_in[3];
    const float* B_re   = (const float*)d_in[4];
    const float* B_im   = (const float*)d_in[5];
    const float* C_re   = (const float*)d_in[6];
    const float* C_im   = (const float*)d_in[7];
    const float* log_dt = (const float*)d_in[8];
    float* out = (float*)d_out;

    (void)in_sizes; (void)n_in; (void)out_size;

    cudaFuncSetAttribute(ifft_kernel,
                         cudaFuncAttributeMaxDynamicSharedMemorySize,
                         SM_TOTAL_F2 * (int)sizeof(float2));

    dim3 grid1(4, HH);   // 4*128 threads * 8 l's = 4096 l's per h
    cauchy_kernel<<<grid1, 128>>>(w_re, w_im, p_re, p_im,
                                  B_re, B_im, C_re, C_im, log_dt);

    ifft_kernel<<<HH, IFFT_T, SM_TOTAL_F2 * (int)sizeof(float2)>>>(out);
}

// round 9
// speedup vs baseline: 1.0752x; 1.0752x over previous
#include <cuda_runtime.h>
#include <math.h>

// Problem constants
#define HH      256
#define NPOLES  32
#define LLEN    8192
#define LH      4097
#define MHALF   4096
#define KSTRIDE 4104       // padded row stride (16B-aligned rows)

// Scratch: half-spectrum k_f per (h, l). 256*4104*8B = 8.4 MB.
__device__ float2 g_kf[HH * KSTRIDE];

typedef unsigned long long u64;

// ---- packed f32x2 helpers (sm_100a) ---------------------------------------
__device__ __forceinline__ u64 f2add(u64 a, u64 b) {
    u64 d; asm("add.rn.f32x2 %0,%1,%2;" : "=l"(d) : "l"(a), "l"(b)); return d;
}
__device__ __forceinline__ u64 f2mul(u64 a, u64 b) {
    u64 d; asm("mul.rn.f32x2 %0,%1,%2;" : "=l"(d) : "l"(a), "l"(b)); return d;
}
__device__ __forceinline__ u64 f2fma(u64 a, u64 b, u64 c) {
    u64 d; asm("fma.rn.f32x2 %0,%1,%2,%3;" : "=l"(d) : "l"(a), "l"(b), "l"(c)); return d;
}
__device__ __forceinline__ u64 f2rcp(u64 a) {
    u64 d;
    asm("{\n\t.reg .f32 lo,hi,rl,rh;\n\t"
        "mov.b64 {lo,hi}, %1;\n\t"
        "rcp.approx.f32 rl, lo;\n\t"
        "rcp.approx.f32 rh, hi;\n\t"
        "mov.b64 %0, {rl,rh};\n\t}" : "=l"(d) : "l"(a));
    return d;
}
__device__ __forceinline__ u64 pack2(float x, float y) {
    u64 d; asm("mov.b64 %0, {%1,%2};" : "=l"(d) : "f"(x), "f"(y)); return d;
}
__device__ __forceinline__ void unpack2(u64 a, float& x, float& y) {
    asm("mov.b64 {%0,%1}, %2;" : "=f"(x), "=f"(y) : "l"(a));
}

// per-lane Woodbury epilogue (im accumulators arrive negated)
__device__ __forceinline__ float2 woodbury(
    float r00r, float n00, float r01r, float n01,
    float r10r, float n10, float r11r, float n11, float t)
{
    const float r00i = -n00, r01i = -n01, r10i = -n10, r11i = -n11;
    const float dre  = 1.0f + r11r;
    const float dim  = r11i;
    const float dinv = __frcp_rn(fmaf(dre, dre, dim * dim));
    const float numre = r01r * r10r - r01i * r10i;
    const float numim = r01r * r10i + r01i * r10r;
    const float qre = (numre * dre + numim * dim) * dinv;
    const float qim = (numim * dre - numre * dim) * dinv;
    const float kwre = r00r - qre;
    const float kwim = r00i - qim;
    return make_float2(kwre - kwim * t, fmaf(kwre, t, kwim));
}

// ---------------------------------------------------------------------------
// Kernel 1: Cauchy + rank-1 Woodbury + bilinear scale -> g_kf[h][l]
// (unchanged from R8 — numerically validated form)
// ---------------------------------------------------------------------------
__global__ __launch_bounds__(128) void cauchy_kernel(
    const float* __restrict__ w_re, const float* __restrict__ w_im,
    const float* __restrict__ p_re, const float* __restrict__ p_im,
    const float* __restrict__ B_re, const float* __restrict__ B_im,
    const float* __restrict__ C_re, const float* __restrict__ C_im,
    const float* __restrict__ log_dt)
{
    __shared__ float2 cst[NPOLES][20];

    const int h   = blockIdx.y;
    const int tid = threadIdx.x;

    if (tid < NPOLES) {
        const int n   = tid;
        const int idx = h * NPOLES + n;
        const float dt = expf(log_dt[h]);
        const float wr = w_re[idx] * dt;
        const float wi = w_im[idx] * dt;
        const float Br = B_re[idx], Bi = B_im[idx];
        const float Cr = C_re[idx], Ci = C_im[idx];
        const float Pr = p_re[idx], Pi = p_im[idx];
        const float aw = wr * wr + wi * wi;
        const float cw = wr * wr - wi * wi;
        const float d2 = 2.0f * dt;
        float2* cn = cst[n];
        cn[0] = make_float2(aw, aw);
        cn[1] = make_float2(-aw, -aw);
        cn[2] = make_float2(cw, cw);
        cn[3] = make_float2(4.0f * wr * wr, 4.0f * wr * wr);
        const float VR[4] = { Br * Cr - Bi * Ci,
                              Br * Pr + Bi * Pi,
                              Pr * Cr - Pi * Ci,
                              Pr * Pr + Pi * Pi };
        const float VI[4] = { Br * Ci + Bi * Cr,
                              Bi * Pr - Br * Pi,
                              Pr * Ci + Pi * Cr,
                              0.0f };
        #pragma unroll
        for (int e = 0; e < 4; e++) {
            float v;
            v = -d2 * wr * VR[e];             cn[4 + 4 * e] = make_float2(v, v); // C1
            v =  d2 * wi * VI[e];             cn[5 + 4 * e] = make_float2(v, v); // C2
            v =  d2 * VR[e];                  cn[6 + 4 * e] = make_float2(v, v); // K1
            v =  d2 * 2.0f * wr * wi * VI[e]; cn[7 + 4 * e] = make_float2(v, v); // K2
        }
    }
    __syncthreads();

    // Nyquist bin (z -> inf): k_f = sum_n dt*Re(B*C) = sum 0.5*K1_00
    if (blockIdx.x == 0 && tid == 0) {
        float acc = 0.0f;
        #pragma unroll
        for (int n = 0; n < NPOLES; n++) acc += 0.5f * cst[n][6].x;
        g_kf[h * KSTRIDE + MHALF] = make_float2(acc, 0.0f);
    }

    const int l0 = (blockIdx.x * 128 + tid) * 8;

    float tt[8];
    #pragma unroll
    for (int i = 0; i < 8; i++) {
        float s, c;
        sincospif((float)(l0 + i) * (1.0f / LLEN), &s, &c);
        tt[i] = __fdividef(s, c);
    }
    u64 zz[4], uu[4];
    #pragma unroll
    for (int pr = 0; pr < 4; pr++) {
        zz[pr] = pack2(2.0f * tt[2 * pr], 2.0f * tt[2 * pr + 1]);
        uu[pr] = f2mul(zz[pr], zz[pr]);
    }

    u64 accR[4][4], accN[4][4];
    #pragma unroll
    for (int pr = 0; pr < 4; pr++)
        #pragma unroll
        for (int e = 0; e < 4; e++) { accR[pr][e] = 0; accN[pr][e] = 0; }

    #pragma unroll 2
    for (int n = 0; n < NPOLES; n++) {
        const u64* cn = reinterpret_cast<const u64*>(cst[n]);
        const u64 AW   = cn[0];
        const u64 NAW  = cn[1];
        const u64 CW   = cn[2];
        const u64 FWR2 = cn[3];
        #pragma unroll
        for (int pr = 0; pr < 4; pr++) {
            const u64 u  = uu[pr];
            const u64 c1 = f2add(u, AW);
            const u64 c2 = f2add(u, NAW);
            const u64 c3 = f2add(u, CW);
            const u64 m  = f2fma(c2, c2, f2mul(u, FWR2));
            const u64 iv = f2rcp(m);
            const u64 ti = f2mul(zz[pr], iv);
            const u64 p1 = f2mul(c1, iv);
            const u64 p2 = f2mul(c2, iv);
            const u64 gi = f2mul(c3, ti);
            #pragma unroll
            for (int e = 0; e < 3; e++) {
                accR[pr][e] = f2fma(cn[4 + 4 * e], p1, f2fma(cn[5 + 4 * e], p2, accR[pr][e]));
                accN[pr][e] = f2fma(cn[6 + 4 * e], gi, f2fma(cn[7 + 4 * e], ti, accN[pr][e]));
            }
            accR[pr][3] = f2fma(cn[16], p1, accR[pr][3]);   // v11: vi = 0
            accN[pr][3] = f2fma(cn[18], gi, accN[pr][3]);
        }
    }

    // epilogue
    float rr[8][4], nn[8][4];   // [lane l][entry]
    #pragma unroll
    for (int pr = 0; pr < 4; pr++)
        #pragma unroll
        for (int e = 0; e < 4; e++) {
            unpack2(accR[pr][e], rr[2 * pr][e], rr[2 * pr + 1][e]);
            unpack2(accN[pr][e], nn[2 * pr][e], nn[2 * pr + 1][e]);
        }

    float2 kf[8];
    #pragma unroll
    for (int i = 0; i < 8; i++)
        kf[i] = woodbury(rr[i][0], nn[i][0], rr[i][1], nn[i][1],
                         rr[i][2], nn[i][2], rr[i][3], nn[i][3], tt[i]);

    float2* row = g_kf + h * KSTRIDE;
    #pragma unroll
    for (int i = 0; i < 4; i++)
        reinterpret_cast<float4*>(row + l0 + 2 * i)[0] =
            make_float4(kf[2 * i].x, kf[2 * i].y, kf[2 * i + 1].x, kf[2 * i + 1].y);
}

// ---------------------------------------------------------------------------
// Kernel 2: per-h irfft(8192) via M=4096 radix-8 Stockham inverse FFT.
// 512 threads, 4 stages. Stage 1 fused with the C2R unpack (reads g_kf
// directly); stage 4 writes coalesced float2 directly to gmem.
// ---------------------------------------------------------------------------
#define PADIDX(i) ((i) + ((i) >> 3))
#define IFFT_T 512

__device__ __forceinline__ u64 csub(u64 a, u64 b) {
    const u64 NEG1 = 0xBF800000BF800000ULL;   // (-1.f, -1.f)
    return f2fma(b, NEG1, a);
}
__device__ __forceinline__ u64 cmuli(u64 a) {     // * i : (x,y) -> (-y,x)
    float x, y; unpack2(a, x, y);
    return pack2(-y, x);
}
__device__ __forceinline__ u64 cmul(u64 a, u64 w) {
    float ax, ay, wx, wy; unpack2(a, ax, ay); unpack2(w, wx, wy);
    return pack2(fmaf(ax, wx, -ay * wy), fmaf(ax, wy, ay * wx));
}

// radix-8 inverse butterfly core (sign +i)
__device__ __forceinline__ void bf8(const u64* x, u64* y)
{
    u64 ta = f2add(x[0], x[4]), tb = csub(x[0], x[4]);
    u64 tc = f2add(x[2], x[6]), td = csub(x[2], x[6]);
    u64 E0 = f2add(ta, tc), E2 = csub(ta, tc);
    u64 itd = cmuli(td);
    u64 E1 = f2add(tb, itd), E3 = csub(tb, itd);

    u64 oa = f2add(x[1], x[5]), ob = csub(x[1], x[5]);
    u64 oc = f2add(x[3], x[7]), od = csub(x[3], x[7]);
    u64 O0 = f2add(oa, oc), O2 = csub(oa, oc);
    u64 iod = cmuli(od);
    u64 O1 = f2add(ob, iod), O3 = csub(ob, iod);

    const float SQ = 0.70710678118654752f;
    float o1x, o1y, o3x, o3y;
    unpack2(O1, o1x, o1y); unpack2(O3, o3x, o3y);
    const u64 W1 = pack2(SQ * (o1x - o1y), SQ * (o1x + o1y));   // w^1 * O1
    const u64 W2 = cmuli(O2);                                    // w^2 * O2
    const u64 W3 = pack2(-SQ * (o3x + o3y), SQ * (o3x - o3y));   // w^3 * O3

    y[0] = f2add(E0, O0); y[4] = csub(E0, O0);
    y[1] = f2add(E1, W1); y[5] = csub(E1, W1);
    y[2] = f2add(E2, W2); y[6] = csub(E2, W2);
    y[3] = f2add(E3, W3); y[7] = csub(E3, W3);
}

template<int S, int LS, int M>
__device__ __forceinline__ void mid_stage(const float2* __restrict__ src,
                                          float2* __restrict__ dst,
                                          const float2* __restrict__ twt,
                                          int t)
{
    const int q = t & (S - 1);
    const int p = t >> LS;
    const int base = q + S * p;

    u64 x[8], y[8];
    #pragma unroll
    for (int j = 0; j < 8; j++)
        x[j] = *reinterpret_cast<const u64*>(&src[PADIDX(base + j * 512)]);
    bf8(x, y);

    const int obase = q + S * 8 * p;
    *reinterpret_cast<u64*>(&dst[PADIDX(obase)]) = y[0];
    #pragma unroll
    for (int k = 1; k < 8; k++) {
        const u64 w = *reinterpret_cast<const u64*>(&twt[(k - 1) * M + p]);
        *reinterpret_cast<u64*>(&dst[PADIDX(obase + S * k)]) = cmul(y[k], w);
    }
}

// smem (float2 units): bufA[4608] bufB[4608] tw1[3584] tw8[448] tw64[56]
#define SM_TOTAL_F2 (4608 + 4608 + 3584 + 448 + 56)

__global__ __launch_bounds__(IFFT_T) void ifft_kernel(float* __restrict__ out)
{
    extern __shared__ float2 sh[];
    float2* bufA = sh;
    float2* bufB = sh + 4608;
    float2* tw1  = sh + 9216;
    float2* tw8  = sh + 12800;
    float2* tw64 = sh + 13248;

    const int h   = blockIdx.x;
    const int tid = threadIdx.x;

    // build stage twiddle tables: [k-1][p] = e^{+2pi i p k / Nt}
    for (int i = tid; i < 3584; i += IFFT_T) {
        const int k = (i >> 9) + 1, p = i & 511;
        float s, c; sincospif((float)(p * k) * (1.0f / 2048.0f), &s, &c);
        tw1[i] = make_float2(c, s);
    }
    if (tid < 448) {
        const int k = (tid >> 6) + 1, p = tid & 63;
        float s, c; sincospif((float)(p * k) * (1.0f / 256.0f), &s, &c);
        tw8[tid] = make_float2(c, s);
    }
    if (tid < 56) {
        const int k = (tid >> 3) + 1, p = tid & 7;
        float s, c; sincospif((float)(p * k) * (1.0f / 32.0f), &s, &c);
        tw64[tid] = make_float2(c, s);
    }
    __syncthreads();

    // ---- Stage 1 fused with C2R unpack: read g_kf directly ----
    const float scale = 1.0f / (float)MHALF;
    const float2* __restrict__ K = &g_kf[h * KSTRIDE];
    {
        u64 x[8], y[8];
        #pragma unroll
        for (int j = 0; j < 8; j++) {
            const int k = tid + 512 * j;
            float2 Kk = K[k];
            float2 Km = K[MHALF - k];
            if (k == 0) { Kk.y = 0.0f; Km.y = 0.0f; }
            const float Ere = 0.5f * (Kk.x + Km.x);
            const float Eim = 0.5f * (Kk.y - Km.y);
            const float Dre = 0.5f * (Kk.x - Km.x);
            const float Dim = 0.5f * (Kk.y + Km.y);
            float tws, twc;
            sincospif((float)k * (1.0f / MHALF), &tws, &twc);   // e^{+2pi i k/8192}
            const float Ore = Dre * twc - Dim * tws;
            const float Oim = Dre * tws + Dim * twc;
            x[j] = pack2((Ere - Oim) * scale, (Eim + Ore) * scale);
        }
        bf8(x, y);
        // S=1: q=0, p=tid; outputs at 8*tid + k
        const int obase = 8 * tid;
        *reinterpret_cast<u64*>(&bufB[PADIDX(obase)]) = y[0];
        #pragma unroll
        for (int k = 1; k < 8; k++) {
            const u64 w = *reinterpret_cast<const u64*>(&tw1[(k - 1) * 512 + tid]);
            *reinterpret_cast<u64*>(&bufB[PADIDX(obase + k)]) = cmul(y[k], w);
        }
    }
    __syncthreads();

    mid_stage<8,  3, 64>(bufB, bufA, tw8,  tid);
    __syncthreads();
    mid_stage<64, 6, 8 >(bufA, bufB, tw64, tid);
    __syncthreads();

    // ---- Stage 4: S=512, p=0 (no twiddle), write directly to gmem ----
    {
        u64 x[8], y[8];
        #pragma unroll
        for (int j = 0; j < 8; j++)
            x[j] = *reinterpret_cast<const u64*>(&bufB[PADIDX(tid + j * 512)]);
        bf8(x, y);
        float2* o2 = reinterpret_cast<float2*>(out) + (size_t)h * MHALF;
        #pragma unroll
        for (int k = 0; k < 8; k++)
            *reinterpret_cast<u64*>(&o2[tid + 512 * k]) = y[k];
    }
}

// ---------------------------------------------------------------------------
extern "C" void kernel_launch(void* const* d_in, const int* in_sizes, int n_in,
                              void* d_out, int out_size)
{
    const float* w_re   = (const float*)d_in[0];
    const float* w_im   = (const float*)d_in[1];
    const float* p_re   = (const float*)d_in[2];
    const float* p_im   = (const float*)d_in[3];
    const float* B_re   = (const float*)d_in[4];
    const float* B_im   = (const float*)d_in[5];
    const float* C_re   = (const float*)d_in[6];
    const float* C_im   = (const float*)d_in[7];
    const float* log_dt = (const float*)d_in[8];
    float* out = (float*)d_out;

    (void)in_sizes; (void)n_in; (void)out_size;

    cudaFuncSetAttribute(ifft_kernel,
                         cudaFuncAttributeMaxDynamicSharedMemorySize,
                         SM_TOTAL_F2 * (int)sizeof(float2));

    dim3 grid1(4, HH);   // 4*128 threads * 8 l's = 4096 l's per h
    cauchy_kernel<<<grid1, 128>>>(w_re, w_im, p_re, p_im,
                                  B_re, B_im, C_re, C_im, log_dt);

    ifft_kernel<<<HH, IFFT_T, SM_TOTAL_F2 * (int)sizeof(float2)>>>(out);
}

// round 10
// speedup vs baseline: 1.1365x; 1.0571x over previous
#include <cuda_runtime.h>
#include <math.h>

// Problem constants
#define HH      256
#define NPOLES  32
#define LLEN    8192
#define LH      4097
#define MHALF   4096
#define KSTRIDE 4104       // padded row stride (16B-aligned rows)

// Scratch: half-spectrum k_f per (h, l). 256*4104*8B = 8.4 MB.
__device__ float2 g_kf[HH * KSTRIDE];

typedef unsigned long long u64;

// ---- packed f32x2 helpers (sm_100a) ---------------------------------------
__device__ __forceinline__ u64 f2add(u64 a, u64 b) {
    u64 d; asm("add.rn.f32x2 %0,%1,%2;" : "=l"(d) : "l"(a), "l"(b)); return d;
}
__device__ __forceinline__ u64 f2mul(u64 a, u64 b) {
    u64 d; asm("mul.rn.f32x2 %0,%1,%2;" : "=l"(d) : "l"(a), "l"(b)); return d;
}
__device__ __forceinline__ u64 f2fma(u64 a, u64 b, u64 c) {
    u64 d; asm("fma.rn.f32x2 %0,%1,%2,%3;" : "=l"(d) : "l"(a), "l"(b), "l"(c)); return d;
}
__device__ __forceinline__ u64 f2rcp(u64 a) {
    u64 d;
    asm("{\n\t.reg .f32 lo,hi,rl,rh;\n\t"
        "mov.b64 {lo,hi}, %1;\n\t"
        "rcp.approx.f32 rl, lo;\n\t"
        "rcp.approx.f32 rh, hi;\n\t"
        "mov.b64 %0, {rl,rh};\n\t}" : "=l"(d) : "l"(a));
    return d;
}
__device__ __forceinline__ u64 pack2(float x, float y) {
    u64 d; asm("mov.b64 %0, {%1,%2};" : "=l"(d) : "f"(x), "f"(y)); return d;
}
__device__ __forceinline__ void unpack2(u64 a, float& x, float& y) {
    asm("mov.b64 {%0,%1}, %2;" : "=f"(x), "=f"(y) : "l"(a));
}

// per-lane Woodbury epilogue (im accumulators arrive negated)
__device__ __forceinline__ float2 woodbury(
    float r00r, float n00, float r01r, float n01,
    float r10r, float n10, float r11r, float n11, float t)
{
    const float r00i = -n00, r01i = -n01, r10i = -n10, r11i = -n11;
    const float dre  = 1.0f + r11r;
    const float dim  = r11i;
    const float dinv = __frcp_rn(fmaf(dre, dre, dim * dim));
    const float numre = r01r * r10r - r01i * r10i;
    const float numim = r01r * r10i + r01i * r10r;
    const float qre = (numre * dre + numim * dim) * dinv;
    const float qim = (numim * dre - numre * dim) * dinv;
    const float kwre = r00r - qre;
    const float kwim = r00i - qim;
    return make_float2(kwre - kwim * t, fmaf(kwre, t, kwim));
}

// ---------------------------------------------------------------------------
// Kernel 1: Cauchy + rank-1 Woodbury + bilinear scale -> g_kf[h][l]
// (math identical to R9 — numerically validated; only sincospif -> __sincosf)
// ---------------------------------------------------------------------------
__global__ __launch_bounds__(128) void cauchy_kernel(
    const float* __restrict__ w_re, const float* __restrict__ w_im,
    const float* __restrict__ p_re, const float* __restrict__ p_im,
    const float* __restrict__ B_re, const float* __restrict__ B_im,
    const float* __restrict__ C_re, const float* __restrict__ C_im,
    const float* __restrict__ log_dt)
{
    __shared__ float2 cst[NPOLES][20];

    const int h   = blockIdx.y;
    const int tid = threadIdx.x;

    if (tid < NPOLES) {
        const int n   = tid;
        const int idx = h * NPOLES + n;
        const float dt = expf(log_dt[h]);
        const float wr = w_re[idx] * dt;
        const float wi = w_im[idx] * dt;
        const float Br = B_re[idx], Bi = B_im[idx];
        const float Cr = C_re[idx], Ci = C_im[idx];
        const float Pr = p_re[idx], Pi = p_im[idx];
        const float aw = wr * wr + wi * wi;
        const float cw = wr * wr - wi * wi;
        const float d2 = 2.0f * dt;
        float2* cn = cst[n];
        cn[0] = make_float2(aw, aw);
        cn[1] = make_float2(-aw, -aw);
        cn[2] = make_float2(cw, cw);
        cn[3] = make_float2(4.0f * wr * wr, 4.0f * wr * wr);
        const float VR[4] = { Br * Cr - Bi * Ci,
                              Br * Pr + Bi * Pi,
                              Pr * Cr - Pi * Ci,
                              Pr * Pr + Pi * Pi };
        const float VI[4] = { Br * Ci + Bi * Cr,
                              Bi * Pr - Br * Pi,
                              Pr * Ci + Pi * Cr,
                              0.0f };
        #pragma unroll
        for (int e = 0; e < 4; e++) {
            float v;
            v = -d2 * wr * VR[e];             cn[4 + 4 * e] = make_float2(v, v); // C1
            v =  d2 * wi * VI[e];             cn[5 + 4 * e] = make_float2(v, v); // C2
            v =  d2 * VR[e];                  cn[6 + 4 * e] = make_float2(v, v); // K1
            v =  d2 * 2.0f * wr * wi * VI[e]; cn[7 + 4 * e] = make_float2(v, v); // K2
        }
    }
    __syncthreads();

    // Nyquist bin (z -> inf): k_f = sum_n dt*Re(B*C) = sum 0.5*K1_00
    if (blockIdx.x == 0 && tid == 0) {
        float acc = 0.0f;
        #pragma unroll
        for (int n = 0; n < NPOLES; n++) acc += 0.5f * cst[n][6].x;
        g_kf[h * KSTRIDE + MHALF] = make_float2(acc, 0.0f);
    }

    const int l0 = (blockIdx.x * 128 + tid) * 8;

    const float PI_OVER_L = 3.83495197e-4f;   // pi/8192
    float tt[8];
    #pragma unroll
    for (int i = 0; i < 8; i++) {
        float s, c;
        __sincosf((float)(l0 + i) * PI_OVER_L, &s, &c);
        tt[i] = __fdividef(s, c);
    }
    u64 zz[4], uu[4];
    #pragma unroll
    for (int pr = 0; pr < 4; pr++) {
        zz[pr] = pack2(2.0f * tt[2 * pr], 2.0f * tt[2 * pr + 1]);
        uu[pr] = f2mul(zz[pr], zz[pr]);
    }

    u64 accR[4][4], accN[4][4];
    #pragma unroll
    for (int pr = 0; pr < 4; pr++)
        #pragma unroll
        for (int e = 0; e < 4; e++) { accR[pr][e] = 0; accN[pr][e] = 0; }

    #pragma unroll 2
    for (int n = 0; n < NPOLES; n++) {
        const u64* cn = reinterpret_cast<const u64*>(cst[n]);
        const u64 AW   = cn[0];
        const u64 NAW  = cn[1];
        const u64 CW   = cn[2];
        const u64 FWR2 = cn[3];
        #pragma unroll
        for (int pr = 0; pr < 4; pr++) {
            const u64 u  = uu[pr];
            const u64 c1 = f2add(u, AW);
            const u64 c2 = f2add(u, NAW);
            const u64 c3 = f2add(u, CW);
            const u64 m  = f2fma(c2, c2, f2mul(u, FWR2));
            const u64 iv = f2rcp(m);
            const u64 ti = f2mul(zz[pr], iv);
            const u64 p1 = f2mul(c1, iv);
            const u64 p2 = f2mul(c2, iv);
            const u64 gi = f2mul(c3, ti);
            #pragma unroll
            for (int e = 0; e < 3; e++) {
                accR[pr][e] = f2fma(cn[4 + 4 * e], p1, f2fma(cn[5 + 4 * e], p2, accR[pr][e]));
                accN[pr][e] = f2fma(cn[6 + 4 * e], gi, f2fma(cn[7 + 4 * e], ti, accN[pr][e]));
            }
            accR[pr][3] = f2fma(cn[16], p1, accR[pr][3]);   // v11: vi = 0
            accN[pr][3] = f2fma(cn[18], gi, accN[pr][3]);
        }
    }

    // epilogue
    float rr[8][4], nn[8][4];   // [lane l][entry]
    #pragma unroll
    for (int pr = 0; pr < 4; pr++)
        #pragma unroll
        for (int e = 0; e < 4; e++) {
            unpack2(accR[pr][e], rr[2 * pr][e], rr[2 * pr + 1][e]);
            unpack2(accN[pr][e], nn[2 * pr][e], nn[2 * pr + 1][e]);
        }

    float2 kf[8];
    #pragma unroll
    for (int i = 0; i < 8; i++)
        kf[i] = woodbury(rr[i][0], nn[i][0], rr[i][1], nn[i][1],
                         rr[i][2], nn[i][2], rr[i][3], nn[i][3], tt[i]);

    float2* row = g_kf + h * KSTRIDE;
    #pragma unroll
    for (int i = 0; i < 4; i++)
        reinterpret_cast<float4*>(row + l0 + 2 * i)[0] =
            make_float4(kf[2 * i].x, kf[2 * i].y, kf[2 * i + 1].x, kf[2 * i + 1].y);
}

// ---------------------------------------------------------------------------
// Kernel 2: per-h irfft(8192) via M=4096 radix-16 Stockham inverse FFT.
// 3 stages (S = 1, 16, 256). Stage 1 fused with C2R unpack (gmem in);
// stage 3 writes coalesced gmem out. 256 threads, 16 points/thread.
// ---------------------------------------------------------------------------
#define PAD16(i) ((i) + ((i) >> 4))
#define IFFT_T 256

__device__ __forceinline__ u64 csub(u64 a, u64 b) {
    const u64 NEG1 = 0xBF800000BF800000ULL;   // (-1.f, -1.f)
    return f2fma(b, NEG1, a);
}
__device__ __forceinline__ u64 cmuli(u64 a) {     // * i : (x,y) -> (-y,x)
    float x, y; unpack2(a, x, y);
    return pack2(-y, x);
}
__device__ __forceinline__ u64 cmul(u64 a, u64 w) {
    float ax, ay, wx, wy; unpack2(a, ax, ay); unpack2(w, wx, wy);
    return pack2(fmaf(ax, wx, -ay * wy), fmaf(ax, wy, ay * wx));
}

#define W16C 0.92387953251128674f
#define W16S 0.38268343236508977f
#define SQH  0.70710678118654752f

__device__ __forceinline__ u64 cw1(u64 a) {   // * e^{+i pi/8}
    float x, y; unpack2(a, x, y);
    return pack2(fmaf(x, W16C, -y * W16S), fmaf(x, W16S, y * W16C));
}
__device__ __forceinline__ u64 cw2(u64 a) {   // * e^{+i pi/4}
    float x, y; unpack2(a, x, y);
    return pack2(SQH * (x - y), SQH * (x + y));
}
__device__ __forceinline__ u64 cw3(u64 a) {   // * e^{+i 3pi/8}
    float x, y; unpack2(a, x, y);
    return pack2(fmaf(x, W16S, -y * W16C), fmaf(x, W16C, y * W16S));
}
__device__ __forceinline__ u64 cw6(u64 a) {   // * e^{+i 3pi/4}
    float x, y; unpack2(a, x, y);
    return pack2(-SQH * (x + y), SQH * (x - y));
}
__device__ __forceinline__ u64 cw9(u64 a) {   // * e^{+i 9pi/8} = -e^{+i pi/8}
    float x, y; unpack2(a, x, y);
    return pack2(fmaf(y, W16S, -x * W16C), fmaf(x, -W16S, -y * W16C));
}

// inverse DFT4 (sign +i)
__device__ __forceinline__ void dft4i(u64 a, u64 b, u64 c, u64 d,
                                      u64& y0, u64& y1, u64& y2, u64& y3)
{
    u64 t0 = f2add(a, c), t1 = csub(a, c);
    u64 t2 = f2add(b, d), t3 = csub(b, d);
    u64 it3 = cmuli(t3);
    y0 = f2add(t0, t2); y2 = csub(t0, t2);
    y1 = f2add(t1, it3); y3 = csub(t1, it3);
}

// inverse radix-16 butterfly: Y[k] = sum_j x[j] e^{+2pi i jk/16}
__device__ __forceinline__ void bf16(const u64* x, u64* y)
{
    u64 G0[4], G1[4], G2[4], G3[4];
    dft4i(x[0], x[4], x[8],  x[12], G0[0], G0[1], G0[2], G0[3]);
    dft4i(x[1], x[5], x[9],  x[13], G1[0], G1[1], G1[2], G1[3]);
    dft4i(x[2], x[6], x[10], x[14], G2[0], G2[1], G2[2], G2[3]);
    dft4i(x[3], x[7], x[11], x[15], G3[0], G3[1], G3[2], G3[3]);

    G1[1] = cw1(G1[1]);  G1[2] = cw2(G1[2]);   G1[3] = cw3(G1[3]);
    G2[1] = cw2(G2[1]);  G2[2] = cmuli(G2[2]); G2[3] = cw6(G2[3]);
    G3[1] = cw3(G3[1]);  G3[2] = cw6(G3[2]);   G3[3] = cw9(G3[3]);

    dft4i(G0[0], G1[0], G2[0], G3[0], y[0], y[4], y[8],  y[12]);
    dft4i(G0[1], G1[1], G2[1], G3[1], y[1], y[5], y[9],  y[13]);
    dft4i(G0[2], G1[2], G2[2], G3[2], y[2], y[6], y[10], y[14]);
    dft4i(G0[3], G1[3], G2[3], G3[3], y[3], y[7], y[11], y[15]);
}

// smem (float2 units): bufA[4352] bufB[4352] tw1[3840] tw2[240]
#define SM_TOTAL_F2 (4352 + 4352 + 3840 + 240)

__global__ __launch_bounds__(IFFT_T) void ifft_kernel(float* __restrict__ out)
{
    extern __shared__ float2 sh[];
    float2* bufA = sh;
    float2* bufB = sh + 4352;
    float2* tw1  = sh + 8704;
    float2* tw2  = sh + 12544;

    const int h   = blockIdx.x;
    const int tid = threadIdx.x;

    // stage twiddle tables: tw_S[k-1][p] = e^{+2pi i S p k / 4096}
    const float A1 = 1.53398078e-3f;    // pi/2048
    #pragma unroll
    for (int r = 0; r < 15; r++) {
        const int i = tid + 256 * r;    // i < 3840
        const int k = r + 1, p = tid;
        float s, c; __sincosf((float)(p * k) * A1, &s, &c);
        tw1[i] = make_float2(c, s);
    }
    if (tid < 240) {
        const int k = (tid >> 4) + 1, p = tid & 15;
        float s, c; __sincosf((float)(p * k) * (2.45436926e-2f), &s, &c);  // 2pi/256
        tw2[tid] = make_float2(c, s);
    }
    __syncthreads();

    // ---- Stage 1 fused with C2R unpack: read g_kf directly ----
    const float scale = 1.0f / (float)MHALF;
    const float A2 = 7.66990394e-4f;    // pi/4096
    const float2* __restrict__ K = &g_kf[h * KSTRIDE];
    {
        u64 x[16], y[16];
        #pragma unroll
        for (int j = 0; j < 16; j++) {
            const int k = tid + 256 * j;
            float2 Kk = K[k];
            float2 Km = K[MHALF - k];
            if (k == 0) { Kk.y = 0.0f; Km.y = 0.0f; }
            const float Ere = 0.5f * (Kk.x + Km.x);
            const float Eim = 0.5f * (Kk.y - Km.y);
            const float Dre = 0.5f * (Kk.x - Km.x);
            const float Dim = 0.5f * (Kk.y + Km.y);
            float tws, twc;
            __sincosf((float)k * A2, &tws, &twc);   // e^{+2pi i k/8192}
            const float Ore = Dre * twc - Dim * tws;
            const float Oim = Dre * tws + Dim * twc;
            x[j] = pack2((Ere - Oim) * scale, (Eim + Ore) * scale);
        }
        bf16(x, y);
        // S=1: q=0, p=tid; outputs at 16*tid + k
        const int obase = 16 * tid;
        *reinterpret_cast<u64*>(&bufB[PAD16(obase)]) = y[0];
        #pragma unroll
        for (int k = 1; k < 16; k++) {
            const u64 w = *reinterpret_cast<const u64*>(&tw1[(k - 1) * 256 + tid]);
            *reinterpret_cast<u64*>(&bufB[PAD16(obase + k)]) = cmul(y[k], w);
        }
    }
    __syncthreads();

    // ---- Stage 2: S=16 ----
    {
        const int q = tid & 15, p = tid >> 4;
        const int base = q + 16 * p;
        u64 x[16], y[16];
        #pragma unroll
        for (int j = 0; j < 16; j++)
            x[j] = *reinterpret_cast<const u64*>(&bufB[PAD16(base + 256 * j)]);
        bf16(x, y);
        const int obase = q + 256 * p;
        *reinterpret_cast<u64*>(&bufA[PAD16(obase)]) = y[0];
        #pragma unroll
        for (int k = 1; k < 16; k++) {
            const u64 w = *reinterpret_cast<const u64*>(&tw2[(k - 1) * 16 + p]);
            *reinterpret_cast<u64*>(&bufA[PAD16(obase + 16 * k)]) = cmul(y[k], w);
        }
    }
    __syncthreads();

    // ---- Stage 3: S=256, p=0 (no twiddle), coalesced gmem writes ----
    {
        u64 x[16], y[16];
        #pragma unroll
        for (int j = 0; j < 16; j++)
            x[j] = *reinterpret_cast<const u64*>(&bufA[PAD16(tid + 256 * j)]);
        bf16(x, y);
        float2* o2 = reinterpret_cast<float2*>(out) + (size_t)h * MHALF;
        #pragma unroll
        for (int k = 0; k < 16; k++)
            *reinterpret_cast<u64*>(&o2[tid + 256 * k]) = y[k];
    }
}

// ---------------------------------------------------------------------------
extern "C" void kernel_launch(void* const* d_in, const int* in_sizes, int n_in,
                              void* d_out, int out_size)
{
    const float* w_re   = (const float*)d_in[0];
    const float* w_im   = (const float*)d_in[1];
    const float* p_re   = (const float*)d_in[2];
    const float* p_im   = (const float*)d_in[3];
    const float* B_re   = (const float*)d_in[4];
    const float* B_im   = (const float*)d_in[5];
    const float* C_re   = (const float*)d_in[6];
    const float* C_im   = (const float*)d_in[7];
    const float* log_dt = (const float*)d_in[8];
    float* out = (float*)d_out;

    (void)in_sizes; (void)n_in; (void)out_size;

    cudaFuncSetAttribute(ifft_kernel,
                         cudaFuncAttributeMaxDynamicSharedMemorySize,
                         SM_TOTAL_F2 * (int)sizeof(float2));

    dim3 grid1(4, HH);   // 4*128 threads * 8 l's = 4096 l's per h
    cauchy_kernel<<<grid1, 128>>>(w_re, w_im, p_re, p_im,
                                  B_re, B_im, C_re, C_im, log_dt);

    ifft_kernel<<<HH, IFFT_T, SM_TOTAL_F2 * (int)sizeof(float2)>>>(out);
}